// round 12
// baseline (speedup 1.0000x reference)
#include <cuda_runtime.h>
#include <cuda_bf16.h>
#include <math.h>

// CONVERGED FINAL (best scored: dur 43.456us, kernel 40.5us, DRAM 68.3%).
// inp [16,4096,512] f32, lengths [16] i32 -> out [16,4096,513] f32:
//   out[b,s,0:512] = inp[b,s,:]
//   out[b,s,512]   = (s < len[b]) ? cos(s/max(len,1)*pi) : 0
//
// Irreducible 1R+1W copy (~269 MB). Measured at the HBM3e mixed R/W stream
// ceiling: 6.6 TB/s wallclock (83% of spec). Six variants tested across
// load/store alignment, unroll depth, cache policy, smem staging, CTA shape —
// all bracket the same wall; this one wins both kernel time and scored dur.
// Structure: one 128-thread CTA per row; aligned LDG.128.CS + coalesced
// scalar STG.CS; thread 0 emits the positional-cosine channel.

#define B_DIM 16
#define S_DIM 4096
#define D_DIM 512
#define PI_F 3.14159265358979323846f

__global__ __launch_bounds__(128) void concat_pe_kernel(
    const float* __restrict__ inp,
    const int* __restrict__ lengths,
    float* __restrict__ out)
{
    const int row = blockIdx.x;               // 0 .. B*S-1
    const int tid = threadIdx.x;              // 0 .. 127
    const int s = row & (S_DIM - 1);
    const int b = row >> 12;                  // row / 4096

    // Vector streaming load: 128 threads x float4 = 512 floats, 16B-aligned.
    const float4* src = reinterpret_cast<const float4*>(inp + (size_t)row * D_DIM);
    float4 v = __ldcs(src + tid);

    // Output row base: row * 513 floats — 4B-aligned, coalesced scalar stores.
    float* dst = out + (size_t)row * (D_DIM + 1);
    const int c = tid * 4;
    __stcs(dst + c + 0, v.x);
    __stcs(dst + c + 1, v.y);
    __stcs(dst + c + 2, v.z);
    __stcs(dst + c + 3, v.w);

    if (tid == 0) {
        const int len = __ldg(&lengths[b]);
        float pe = 0.0f;
        if (s < len) {
            float fl = fmaxf((float)len, 1.0f);
            pe = cosf((float)s / fl * PI_F);
        }
        __stcs(dst + D_DIM, pe);
    }
}

extern "C" void kernel_launch(void* const* d_in, const int* in_sizes, int n_in,
                              void* d_out, int out_size) {
    const float* inp = (const float*)d_in[0];
    const int* lengths = (const int*)d_in[1];
    float* out = (float*)d_out;

    dim3 grid(B_DIM * S_DIM);  // 65536 rows
    dim3 block(128);
    concat_pe_kernel<<<grid, block>>>(inp, lengths, out);
}